// round 10
// baseline (speedup 1.0000x reference)
#include <cuda_runtime.h>
#include <float.h>

#define Bv 64
#define Nv 1024
#define Dv 128
#define Kv 6
#define CHUNKS 16         // 64 rows per main block, grid = 16 x 64 = 1024
#define RPB 64
#define THR 128           // 4 warps x 16 rows x 2 parity-lanes
#define MARGIN 0.001f     // > 1/1024 bucket width (counting-sort disorder bound)

typedef unsigned long long ull;

__device__ float  g_ABC[Kv * Dv * 3];           // [k][d][{A,B,C}]
__device__ float  g_partial[Bv * CHUNKS * Dv];  // [b][chunk][d]
__device__ float4 g_pts[Bv * Nv];               // (xb, yb, deadline, orig)
__device__ float2 g_p0[Bv * Nv];                // (x0, y0) sorted order
__device__ int    g_count;                      // completion counter

// ---- packed f32x2 helpers (per-half rn == scalar rounding) ----
__device__ __forceinline__ ull f2add(ull a, ull b) {
    ull r; asm("add.rn.f32x2 %0,%1,%2;" : "=l"(r) : "l"(a), "l"(b)); return r;
}
__device__ __forceinline__ ull f2mul(ull a, ull b) {
    ull r; asm("mul.rn.f32x2 %0,%1,%2;" : "=l"(r) : "l"(a), "l"(b)); return r;
}
__device__ __forceinline__ ull f2fma(ull a, ull b, ull c) {
    ull r; asm("fma.rn.f32x2 %0,%1,%2,%3;" : "=l"(r) : "l"(a), "l"(b), "l"(c)); return r;
}
__device__ __forceinline__ ull f2pack(float lo, float hi) {
    ull r; asm("mov.b64 %0,{%1,%2};" : "=l"(r) : "f"(lo), "f"(hi)); return r;
}
__device__ __forceinline__ void f2unpack(ull v, float& lo, float& hi) {
    asm("mov.b64 {%0,%1},%2;" : "=f"(lo), "=f"(hi) : "l"(v));
}

// ---------------------------------------------------------------------------
// Setup: blocks 0..63  -> per-batch counting sort by x-bucket (1024 buckets)
//        blocks 64..111 -> ABC weight fold (one warp per (k,d))
// ---------------------------------------------------------------------------
__global__ __launch_bounds__(512) void setup_kernel(
    const float* __restrict__ loc, const float* __restrict__ deadline,
    const float* __restrict__ W2d, const float* __restrict__ b2d,
    const float* __restrict__ Wnb)
{
    __shared__ int cnt[Nv];
    __shared__ int wsum[16];
    const int t = threadIdx.x;

    if (blockIdx.x >= Bv) {
        int wid  = (blockIdx.x - Bv) * 16 + (t >> 5);
        int k    = wid >> 7, d = wid & (Dv - 1);
        int lane = t & 31;
        const float4* w4 = (const float4*)(Wnb + (size_t)d * (Kv * Dv) + k * Dv);
        float4 v  = w4[lane];
        const float4* w2 = (const float4*)W2d;
        float4 p0 = w2[lane * 2], p1 = w2[lane * 2 + 1];
        float4 bb = ((const float4*)b2d)[lane];
        float A = fmaf(v.x, p0.x, fmaf(v.y, p0.z, fmaf(v.z, p1.x, v.w * p1.z)));
        float B = fmaf(v.x, p0.y, fmaf(v.y, p0.w, fmaf(v.z, p1.y, v.w * p1.w)));
        float C = fmaf(v.x, bb.x, fmaf(v.y, bb.y, fmaf(v.z, bb.z, v.w * bb.w)));
#pragma unroll
        for (int s = 16; s > 0; s >>= 1) {
            A += __shfl_xor_sync(0xffffffffu, A, s);
            B += __shfl_xor_sync(0xffffffffu, B, s);
            C += __shfl_xor_sync(0xffffffffu, C, s);
        }
        if (lane == 0) {
            int base = (k * Dv + d) * 3;
            g_ABC[base + 0] = A; g_ABC[base + 1] = B; g_ABC[base + 2] = C;
        }
        return;
    }

    const int b = blockIdx.x;
    const float2* lb = (const float2*)(loc + (size_t)b * Nv * 2);
    const float2* l0 = (const float2*)loc;

    cnt[t] = 0; cnt[t + 512] = 0;
    float2 pa = lb[t], pb = lb[t + 512];
    float2 qa = l0[t], qb = l0[t + 512];
    float dla = deadline[(size_t)b * Nv + t];
    float dlb = deadline[(size_t)b * Nv + t + 512];
    __syncthreads();
    int bka = min((int)(pa.x * 1024.0f), Nv - 1);
    int bkb = min((int)(pb.x * 1024.0f), Nv - 1);
    atomicAdd(&cnt[bka], 1);
    atomicAdd(&cnt[bkb], 1);
    __syncthreads();

    int c0 = cnt[2 * t], c1 = cnt[2 * t + 1];
    int s  = c0 + c1;
    int lane = t & 31;
    int v = s;
#pragma unroll
    for (int o = 1; o < 32; o <<= 1) {
        int u = __shfl_up_sync(0xffffffffu, v, o);
        if (lane >= o) v += u;
    }
    if (lane == 31) wsum[t >> 5] = v;
    __syncthreads();
    if (t < 16) {
        int wv = wsum[t], vv = wv;
#pragma unroll
        for (int o = 1; o < 16; o <<= 1) {
            int u = __shfl_up_sync(0x0000ffffu, vv, o);
            if (t >= o) vv += u;
        }
        wsum[t] = vv - wv;
    }
    __syncthreads();
    int excl = wsum[t >> 5] + (v - s);
    cnt[2 * t]     = excl;
    cnt[2 * t + 1] = excl + c0;
    __syncthreads();

    int posA = atomicAdd(&cnt[bka], 1);
    g_pts[(size_t)b * Nv + posA] = make_float4(pa.x, pa.y, dla, __int_as_float(t));
    g_p0[(size_t)b * Nv + posA]  = qa;
    int posB = atomicAdd(&cnt[bkb], 1);
    g_pts[(size_t)b * Nv + posB] = make_float4(pb.x, pb.y, dlb, __int_as_float(t + 512));
    g_p0[(size_t)b * Nv + posB]  = qb;
}

// ---------------------------------------------------------------------------
// Main: 128 threads = 4 warps; warp owns 16 consecutive sorted rows; two
// lanes per row scan disjoint interleaved candidate classes two-sided,
// mask-guarded (no divergent branches), then shfl-merge the two top-6 lists.
// ---------------------------------------------------------------------------
__global__ __launch_bounds__(THR) void main_kernel(
    const float* __restrict__ W3d, const float* __restrict__ b3d,
    const float* __restrict__ bnb,
    const float* __restrict__ depot, const float* __restrict__ Wdep,
    const float* __restrict__ bdep, float* __restrict__ h_out)
{
    __shared__ __align__(16) float2 sxyv[Nv];      // sorted batch-b coords  8 KB
    __shared__ __align__(16) float2 s0s[Nv];       // batch-0 coords, sorted 8 KB
    __shared__ float4 srow[RPB];                   // (x,y,deadline,orig)    1 KB
    __shared__ __align__(16) float2 snb[RPB * Kv]; // neighbor b0 coords     3 KB
    __shared__ float4 sW3[Dv];                     // (w0,w1,w2, base)       2 KB
    __shared__ __align__(16) float2 sAB[Kv * Dv];  // (A_k[d], B_k[d])       6 KB
    __shared__ int    sLast;

    const int b = blockIdx.y, chunk = blockIdx.x, t = threadIdx.x;

    {
        const float4* gp = g_pts + (size_t)b * Nv;
        const float2* g0 = g_p0  + (size_t)b * Nv;
#pragma unroll
        for (int i = 0; i < Nv / THR; i++) {
            float4 q = gp[i * THR + t];
            sxyv[i * THR + t] = make_float2(q.x, q.y);
            s0s[i * THR + t]  = g0[i * THR + t];
        }
        if (t < RPB) srow[t] = gp[chunk * RPB + t];
    }
    {
        float sumC = 0.f;
#pragma unroll
        for (int k = 0; k < Kv; k++) {
            int base = (k * Dv + t) * 3;
            sAB[k * Dv + t] = make_float2(g_ABC[base], g_ABC[base + 1]);
            sumC += g_ABC[base + 2];
        }
        sW3[t] = make_float4(W3d[t * 3 + 0], W3d[t * 3 + 1], W3d[t * 3 + 2],
                             b3d[t] + bnb[t] + sumC);
    }
    __syncthreads();

    // ---- phase 2: parity-split two-sided scan ----
    const int w     = t >> 5, lane = t & 31;
    const int r     = lane & 15;           // row within warp group
    const int par   = lane >> 4;           // candidate class 0/1
    const int gbase = chunk * RPB + w * 16;
    const int p     = gbase + r;           // this row's sorted position
    const int rloc  = w * 16 + r;
    const float2 m  = sxyv[p];
    const ull negm  = f2pack(-m.x, -m.y);

    float d0 = FLT_MAX, d1 = FLT_MAX, d2 = FLT_MAX,
          d3 = FLT_MAX, d4 = FLT_MAX, d5 = FLT_MAX;
    int   i0 = 0, i1 = 0, i2 = 0, i3 = 0, i4 = 0, i5 = 0;

#define INS(dd, cj)  do {                                                    \
        bool c0 = dd < d0, c1 = dd < d1, c2 = dd < d2,                       \
             c3 = dd < d3, c4 = dd < d4, c5 = dd < d5;                       \
        float m0 = fmaxf(d0, dd), m1 = fmaxf(d1, dd), m2 = fmaxf(d2, dd),    \
              m3 = fmaxf(d3, dd), m4 = fmaxf(d4, dd);                        \
        int   w0 = c0 ? i0 : cj, w1 = c1 ? i1 : cj, w2 = c2 ? i2 : cj,       \
              w3 = c3 ? i3 : cj, w4 = c4 ? i4 : cj;                          \
        d5 = c5 ? m4 : d5;  i5 = c5 ? w4 : i5;                               \
        d4 = c4 ? m3 : d4;  i4 = c4 ? w3 : i4;                               \
        d3 = c3 ? m2 : d3;  i3 = c3 ? w2 : i3;                               \
        d2 = c2 ? m1 : d2;  i2 = c2 ? w1 : i2;                               \
        d1 = c1 ? m0 : d1;  i1 = c1 ? w0 : i1;                               \
        d0 = c0 ? dd : d0;  i0 = c0 ? cj : i0;                               \
    } while (0)

    // masked CAND: invalid j -> dd = FLT_MAX (no-op insert), clamped address
#define CANDM(jj, VALID, DX) {                                              \
        int jc   = VALID ? (jj) : 0;                                        \
        ull cvu  = *(const ull*)&sxyv[jc];                                  \
        ull diff = f2add(cvu, negm);                                        \
        ull sq   = f2mul(diff, diff);                                       \
        float qlo, qhi, dlo, dhi;                                           \
        f2unpack(sq, qlo, qhi);                                             \
        f2unpack(diff, dlo, dhi); (void)dhi;                                \
        DX = dlo;                                                           \
        float dd = VALID ? __fadd_rn(qlo, qhi) : FLT_MAX;                   \
        INS(dd, jc);                                                        \
    }

    {   // core: 8 candidates of own class inside [gbase, gbase+16)
        float dxx;
#pragma unroll
        for (int q = 0; q < 8; q++) CANDM(gbase + par + 2 * q, true, dxx);
    }
    {   // left wing: j = gbase-1-par, step -2; pairs per vote
        int j = gbase - 1 - par;
        bool go = (gbase > 0);
        while (go) {
            bool v0 = (j >= 0), v1 = (j - 2 >= 0);
            float x0d, x1d;
            CANDM(j,     v0, x0d);
            CANDM(j - 2, v1, x1d);
            float ax = fmaxf(fabsf(x1d) - MARGIN, 0.f);
            go = __any_sync(0xffffffffu, v1 && (__fmul_rn(ax, ax) <= d5));
            j -= 4;
        }
    }
    {   // right wing: j = gbase+16+par, step +2; pairs per vote
        int j = gbase + 16 + par;
        bool go = (gbase + 16 < Nv);
        while (go) {
            bool v0 = (j < Nv), v1 = (j + 2 < Nv);
            float x0d, x1d;
            CANDM(j,     v0, x0d);
            CANDM(j + 2, v1, x1d);
            float ax = fmaxf(fabsf(x1d) - MARGIN, 0.f);
            go = __any_sync(0xffffffffu, v1 && (__fmul_rn(ax, ax) <= d5));
            j += 4;
        }
    }
#undef CANDM
#undef INS

    {   // merge the two class lists via shfl (disjoint; ties impossible,
        // but keep a symmetric preference for determinism)
        float e0 = __shfl_xor_sync(0xffffffffu, d0, 16);
        float e1 = __shfl_xor_sync(0xffffffffu, d1, 16);
        float e2 = __shfl_xor_sync(0xffffffffu, d2, 16);
        float e3 = __shfl_xor_sync(0xffffffffu, d3, 16);
        float e4 = __shfl_xor_sync(0xffffffffu, d4, 16);
        float e5 = __shfl_xor_sync(0xffffffffu, d5, 16);
        int   z0 = __shfl_xor_sync(0xffffffffu, i0, 16);
        int   z1 = __shfl_xor_sync(0xffffffffu, i1, 16);
        int   z2 = __shfl_xor_sync(0xffffffffu, i2, 16);
        int   z3 = __shfl_xor_sync(0xffffffffu, i3, 16);
        int   z4 = __shfl_xor_sync(0xffffffffu, i4, 16);
        int   z5 = __shfl_xor_sync(0xffffffffu, i5, 16);
#pragma unroll
        for (int s = 0; s < Kv; s++) {
            bool ta = (d0 < e0) || (d0 == e0 && par == 0);
            int sel = ta ? i0 : z0;
            if ((par == 0) == (s < 3))           // par0 writes 0..2, par1 3..5
                snb[rloc * Kv + s] = s0s[sel];
            if (ta) { d0=d1; d1=d2; d2=d3; d3=d4; d4=d5; d5=FLT_MAX;
                      i0=i1; i1=i2; i2=i3; i3=i4; i4=i5; }
            else    { e0=e1; e1=e2; e2=e3; e3=e4; e4=e5; e5=FLT_MAX;
                      z0=z1; z1=z2; z2=z3; z3=z4; z4=z5; }
        }
    }
    __syncthreads();

    // ---- phase 3: thread t = dim d; FFMA2 over packed pairs ----
    const int d = t;
    const float4 wv = sW3[d];
    const ull w01 = f2pack(wv.x, wv.y);
    ull AB[Kv];
#pragma unroll
    for (int k = 0; k < Kv; k++) AB[k] = *(const ull*)&sAB[k * Dv + d];

    float acc = 0.f;
#pragma unroll 4
    for (int rr = 0; rr < RPB; rr++) {
        float4 rd = srow[rr];                    // broadcast LDS.128
        const ulonglong2* nbp = (const ulonglong2*)(snb + rr * Kv);
        ulonglong2 q0 = nbp[0], q1 = nbp[1], q2 = nbp[2];   // 3x LDS.128
        ull s2 = f2pack(wv.w, __fmul_rn(rd.z, wv.z));       // (base, dl*w2)
        s2 = f2fma(f2pack(rd.x, rd.y), w01, s2);
        s2 = f2fma(q0.x, AB[0], s2);
        s2 = f2fma(q0.y, AB[1], s2);
        s2 = f2fma(q1.x, AB[2], s2);
        s2 = f2fma(q1.y, AB[3], s2);
        s2 = f2fma(q2.x, AB[4], s2);
        s2 = f2fma(q2.y, AB[5], s2);
        float lo, hi; f2unpack(s2, lo, hi);
        float v = __fadd_rn(lo, hi);
        v = fmaxf(v, 0.01f * v);                 // leaky_relu(0.01)
        int orow = __float_as_int(rd.w);
        h_out[((size_t)b * 1025 + 1 + orow) * Dv + d] = v;
        acc += v;
    }
    g_partial[((size_t)b * CHUNKS + chunk) * Dv + d] = acc;

    // ---- fused tail: last finishing block computes depot row + means ----
    __threadfence();
    if (t == 0) sLast = (atomicAdd(&g_count, 1) == CHUNKS * Bv - 1) ? 1 : 0;
    __syncthreads();
    if (sLast) {
        float w0 = Wdep[t * 2 + 0], w1 = Wdep[t * 2 + 1], bd = bdep[t];
        for (int bb = 0; bb < Bv; bb++) {
            float v = bd;
            v = fmaf(depot[bb * 2 + 0], w0, v);
            v = fmaf(depot[bb * 2 + 1], w1, v);
            v = fmaxf(v, 0.01f * v);
            h_out[(size_t)bb * 1025 * Dv + t] = v;       // h[bb, 0, d]
            float s = v;
#pragma unroll
            for (int c = 0; c < CHUNKS; c++)
                s += g_partial[((size_t)bb * CHUNKS + c) * Dv + t];
            h_out[(size_t)Bv * 1025 * Dv + bb * Dv + t] = s / 1025.0f;
        }
        if (t == 0) g_count = 0;                 // reset for next graph replay
    }
}

// ---------------------------------------------------------------------------
extern "C" void kernel_launch(void* const* d_in, const int* in_sizes, int n_in,
                              void* d_out, int out_size)
{
    const float* loc      = (const float*)d_in[0];
    const float* deadline = (const float*)d_in[1];
    const float* depot    = (const float*)d_in[2];
    const float* W3d      = (const float*)d_in[3];
    const float* b3d      = (const float*)d_in[4];
    const float* W2d      = (const float*)d_in[5];
    const float* b2d      = (const float*)d_in[6];
    const float* Wnb      = (const float*)d_in[7];
    const float* bnb      = (const float*)d_in[8];
    const float* Wdep     = (const float*)d_in[9];
    const float* bdep     = (const float*)d_in[10];
    float* out = (float*)d_out;

    setup_kernel<<<Bv + 48, 512>>>(loc, deadline, W2d, b2d, Wnb);
    dim3 grid(CHUNKS, Bv);
    main_kernel<<<grid, THR>>>(W3d, b3d, bnb, depot, Wdep, bdep, out);
}

// round 13
// speedup vs baseline: 1.1358x; 1.1358x over previous
#include <cuda_runtime.h>
#include <float.h>

#define Bv 64
#define Nv 1024
#define Dv 128
#define Kv 6
#define CHUNKS 8          // 128 rows per main block, grid = 8 x 64 = 512
#define RPB 128
#define THR 128
#define MARGIN 0.001f     // > 1/1024 bucket width (counting-sort disorder bound)

typedef unsigned long long ull;

__device__ float  g_ABC[Kv * Dv * 3];           // [k][d][{A,B,C}]
__device__ float  g_partial[Bv * CHUNKS * Dv];  // [b][chunk][d]
__device__ float4 g_pts[Bv * Nv];               // (xb, yb, deadline, orig)
__device__ float2 g_p0[Bv * Nv];                // (x0, y0) sorted order
__device__ int    g_count;                      // completion counter

// ---- packed f32x2 helpers (per-half rn == scalar rounding) ----
__device__ __forceinline__ ull f2add(ull a, ull b) {
    ull r; asm("add.rn.f32x2 %0,%1,%2;" : "=l"(r) : "l"(a), "l"(b)); return r;
}
__device__ __forceinline__ ull f2mul(ull a, ull b) {
    ull r; asm("mul.rn.f32x2 %0,%1,%2;" : "=l"(r) : "l"(a), "l"(b)); return r;
}
__device__ __forceinline__ ull f2fma(ull a, ull b, ull c) {
    ull r; asm("fma.rn.f32x2 %0,%1,%2,%3;" : "=l"(r) : "l"(a), "l"(b), "l"(c)); return r;
}
__device__ __forceinline__ ull f2pack(float lo, float hi) {
    ull r; asm("mov.b64 %0,{%1,%2};" : "=l"(r) : "f"(lo), "f"(hi)); return r;
}
__device__ __forceinline__ void f2unpack(ull v, float& lo, float& hi) {
    asm("mov.b64 {%0,%1},%2;" : "=f"(lo), "=f"(hi) : "l"(v));
}

// ---------------------------------------------------------------------------
// Setup: blocks 0..63  -> per-batch counting sort by x-bucket (1024 buckets)
//        blocks 64..111 -> ABC weight fold (one warp per (k,d))
// ---------------------------------------------------------------------------
__global__ __launch_bounds__(512) void setup_kernel(
    const float* __restrict__ loc, const float* __restrict__ deadline,
    const float* __restrict__ W2d, const float* __restrict__ b2d,
    const float* __restrict__ Wnb)
{
    __shared__ int cnt[Nv];
    __shared__ int wsum[16];
    const int t = threadIdx.x;

    if (blockIdx.x >= Bv) {
        int wid  = (blockIdx.x - Bv) * 16 + (t >> 5);
        int k    = wid >> 7, d = wid & (Dv - 1);
        int lane = t & 31;
        const float4* w4 = (const float4*)(Wnb + (size_t)d * (Kv * Dv) + k * Dv);
        float4 v  = w4[lane];
        const float4* w2 = (const float4*)W2d;
        float4 p0 = w2[lane * 2], p1 = w2[lane * 2 + 1];
        float4 bb = ((const float4*)b2d)[lane];
        float A = fmaf(v.x, p0.x, fmaf(v.y, p0.z, fmaf(v.z, p1.x, v.w * p1.z)));
        float B = fmaf(v.x, p0.y, fmaf(v.y, p0.w, fmaf(v.z, p1.y, v.w * p1.w)));
        float C = fmaf(v.x, bb.x, fmaf(v.y, bb.y, fmaf(v.z, bb.z, v.w * bb.w)));
#pragma unroll
        for (int s = 16; s > 0; s >>= 1) {
            A += __shfl_xor_sync(0xffffffffu, A, s);
            B += __shfl_xor_sync(0xffffffffu, B, s);
            C += __shfl_xor_sync(0xffffffffu, C, s);
        }
        if (lane == 0) {
            int base = (k * Dv + d) * 3;
            g_ABC[base + 0] = A; g_ABC[base + 1] = B; g_ABC[base + 2] = C;
        }
        return;
    }

    const int b = blockIdx.x;
    const float2* lb = (const float2*)(loc + (size_t)b * Nv * 2);
    const float2* l0 = (const float2*)loc;

    cnt[t] = 0; cnt[t + 512] = 0;
    float2 pa = lb[t], pb = lb[t + 512];
    float2 qa = l0[t], qb = l0[t + 512];
    float dla = deadline[(size_t)b * Nv + t];
    float dlb = deadline[(size_t)b * Nv + t + 512];
    __syncthreads();
    int bka = min((int)(pa.x * 1024.0f), Nv - 1);
    int bkb = min((int)(pb.x * 1024.0f), Nv - 1);
    atomicAdd(&cnt[bka], 1);
    atomicAdd(&cnt[bkb], 1);
    __syncthreads();

    int c0 = cnt[2 * t], c1 = cnt[2 * t + 1];
    int s  = c0 + c1;
    int lane = t & 31;
    int v = s;
#pragma unroll
    for (int o = 1; o < 32; o <<= 1) {
        int u = __shfl_up_sync(0xffffffffu, v, o);
        if (lane >= o) v += u;
    }
    if (lane == 31) wsum[t >> 5] = v;
    __syncthreads();
    if (t < 16) {
        int wv = wsum[t], vv = wv;
#pragma unroll
        for (int o = 1; o < 16; o <<= 1) {
            int u = __shfl_up_sync(0x0000ffffu, vv, o);
            if (t >= o) vv += u;
        }
        wsum[t] = vv - wv;
    }
    __syncthreads();
    int excl = wsum[t >> 5] + (v - s);
    cnt[2 * t]     = excl;
    cnt[2 * t + 1] = excl + c0;
    __syncthreads();

    int posA = atomicAdd(&cnt[bka], 1);
    g_pts[(size_t)b * Nv + posA] = make_float4(pa.x, pa.y, dla, __int_as_float(t));
    g_p0[(size_t)b * Nv + posA]  = qa;
    int posB = atomicAdd(&cnt[bkb], 1);
    g_pts[(size_t)b * Nv + posB] = make_float4(pb.x, pb.y, dlb, __int_as_float(t + 512));
    g_p0[(size_t)b * Nv + posB]  = qb;
}

// ---------------------------------------------------------------------------
// Main: 128 threads = 4 warps; warp w owns rows [w*32, w*32+32); two-sided
// warp-uniform scan with TWO interleaved exact top-6 lists per thread
// (independent select-chains -> 2x ILP), pruned by min(dE5, dO5); exact
// 6-step two-pointer merge at the end.
// ---------------------------------------------------------------------------
__global__ __launch_bounds__(THR) void main_kernel(
    const float* __restrict__ W3d, const float* __restrict__ b3d,
    const float* __restrict__ bnb,
    const float* __restrict__ depot, const float* __restrict__ Wdep,
    const float* __restrict__ bdep, float* __restrict__ h_out)
{
    __shared__ __align__(16) float2 sxyv[Nv];      // sorted batch-b coords  8 KB
    __shared__ __align__(16) float2 s0s[Nv];       // batch-0 coords, sorted 8 KB
    __shared__ float4 srow[RPB];                   // (x,y,deadline,orig)    2 KB
    __shared__ __align__(16) float2 snb[RPB * Kv]; // neighbor b0 coords     6 KB
    __shared__ float4 sW3[Dv];                     // (w0,w1,w2, base)       2 KB
    __shared__ __align__(16) float2 sAB[Kv * Dv];  // (A_k[d], B_k[d])       6 KB
    __shared__ int    sLast;

    const int b = blockIdx.y, chunk = blockIdx.x, t = threadIdx.x;

    {
        const float4* gp = g_pts + (size_t)b * Nv;
        const float2* g0 = g_p0  + (size_t)b * Nv;
#pragma unroll
        for (int i = 0; i < Nv / THR; i++) {
            float4 q = gp[i * THR + t];
            sxyv[i * THR + t] = make_float2(q.x, q.y);
            s0s[i * THR + t]  = g0[i * THR + t];
        }
        srow[t] = gp[chunk * RPB + t];
    }
    {
        float sumC = 0.f;
#pragma unroll
        for (int k = 0; k < Kv; k++) {
            int base = (k * Dv + t) * 3;
            sAB[k * Dv + t] = make_float2(g_ABC[base], g_ABC[base + 1]);
            sumC += g_ABC[base + 2];
        }
        sW3[t] = make_float4(W3d[t * 3 + 0], W3d[t * 3 + 1], W3d[t * 3 + 2],
                             b3d[t] + bnb[t] + sumC);
    }
    __syncthreads();

    // ---- phase 2: warp-uniform two-sided scan, dual exact top-6 lists ----
    const int w    = t >> 5;
    const int base = chunk * RPB + w * 32;
    const int p    = base + (t & 31);
    const float2 m = sxyv[p];
    const ull negm = f2pack(-m.x, -m.y);

    float eA0 = FLT_MAX, eA1 = FLT_MAX, eA2 = FLT_MAX,
          eA3 = FLT_MAX, eA4 = FLT_MAX, eA5 = FLT_MAX;
    int   jA0 = 0, jA1 = 0, jA2 = 0, jA3 = 0, jA4 = 0, jA5 = 0;
    float eB0 = FLT_MAX, eB1 = FLT_MAX, eB2 = FLT_MAX,
          eB3 = FLT_MAX, eB4 = FLT_MAX, eB5 = FLT_MAX;
    int   jB0 = 0, jB1 = 0, jB2 = 0, jB3 = 0, jB4 = 0, jB5 = 0;

    // exact branchless sorted insert (strict <) into a named 6-slot list
#define INS6(dd, cj, d0,d1,d2,d3,d4,d5, i0,i1,i2,i3,i4,i5)  do {             \
        bool c0 = dd < d0, c1 = dd < d1, c2 = dd < d2,                       \
             c3 = dd < d3, c4 = dd < d4, c5 = dd < d5;                       \
        float m0 = fmaxf(d0, dd), m1 = fmaxf(d1, dd), m2 = fmaxf(d2, dd),    \
              m3 = fmaxf(d3, dd), m4 = fmaxf(d4, dd);                        \
        int   w0 = c0 ? i0 : cj, w1 = c1 ? i1 : cj, w2 = c2 ? i2 : cj,       \
              w3 = c3 ? i3 : cj, w4 = c4 ? i4 : cj;                          \
        d5 = c5 ? m4 : d5;  i5 = c5 ? w4 : i5;                               \
        d4 = c4 ? m3 : d4;  i4 = c4 ? w3 : i4;                               \
        d3 = c3 ? m2 : d3;  i3 = c3 ? w2 : i3;                               \
        d2 = c2 ? m1 : d2;  i2 = c2 ? w1 : i2;                               \
        d1 = c1 ? m0 : d1;  i1 = c1 ? w0 : i1;                               \
        d0 = c0 ? dd : d0;  i0 = c0 ? cj : i0;                               \
    } while (0)

#define DIST(jj, DD, DX) {                                                  \
        ull cvu  = *(const ull*)&sxyv[jj];                                  \
        ull diff = f2add(cvu, negm);                                        \
        ull sq   = f2mul(diff, diff);                                       \
        float qlo, qhi, dlo, dhi;                                           \
        f2unpack(sq, qlo, qhi);                                             \
        f2unpack(diff, dlo, dhi); (void)dhi;                                \
        DX = dlo;                                                           \
        DD = __fadd_rn(qlo, qhi);                                           \
    }

#define CAND_A(jj) { float _dd, _dx; DIST(jj, _dd, _dx); (void)_dx;         \
        INS6(_dd, (jj), eA0,eA1,eA2,eA3,eA4,eA5, jA0,jA1,jA2,jA3,jA4,jA5); }
#define CAND_B(jj) { float _dd, _dx; DIST(jj, _dd, _dx); (void)_dx;         \
        INS6(_dd, (jj), eB0,eB1,eB2,eB3,eB4,eB5, jB0,jB1,jB2,jB3,jB4,jB5); }
#define CAND_AX(jj, DX) { float _dd; DIST(jj, _dd, DX);                     \
        INS6(_dd, (jj), eA0,eA1,eA2,eA3,eA4,eA5, jA0,jA1,jA2,jA3,jA4,jA5); }
#define CAND_BX(jj, DX) { float _dd; DIST(jj, _dd, DX);                     \
        INS6(_dd, (jj), eB0,eB1,eB2,eB3,eB4,eB5, jB0,jB1,jB2,jB3,jB4,jB5); }

    {   // core 32 candidates, alternating lists (self dd=0 self-inserts)
#pragma unroll
        for (int q = 0; q < 32; q += 2) { CAND_A(base + q); CAND_B(base + q + 1); }
    }
    {   // leftward, groups of 8, vote on farthest member, thr = min(dA5,dB5)
        int j = base - 1; bool go = (j >= 0);
        while (go && j >= 7) {
            float xd;
            CAND_A(j);   CAND_B(j-1); CAND_A(j-2); CAND_B(j-3);
            CAND_A(j-4); CAND_B(j-5); CAND_A(j-6); CAND_BX(j-7, xd);
            float ax  = fmaxf(fabsf(xd) - MARGIN, 0.f);
            float thr = fminf(eA5, eB5);
            go = __any_sync(0xffffffffu, __fmul_rn(ax, ax) <= thr);
            j -= 8;
        }
        while (go && j >= 0) {
            float xd; CAND_AX(j, xd);
            float ax  = fmaxf(fabsf(xd) - MARGIN, 0.f);
            float thr = fminf(eA5, eB5);
            go = __any_sync(0xffffffffu, __fmul_rn(ax, ax) <= thr);
            j--;
        }
    }
    {   // rightward
        int j = base + 32; bool go = (j < Nv);
        while (go && j <= Nv - 8) {
            float xd;
            CAND_A(j);   CAND_B(j+1); CAND_A(j+2); CAND_B(j+3);
            CAND_A(j+4); CAND_B(j+5); CAND_A(j+6); CAND_BX(j+7, xd);
            float ax  = fmaxf(fabsf(xd) - MARGIN, 0.f);
            float thr = fminf(eA5, eB5);
            go = __any_sync(0xffffffffu, __fmul_rn(ax, ax) <= thr);
            j += 8;
        }
        while (go && j < Nv) {
            float xd; CAND_AX(j, xd);
            float ax  = fmaxf(fabsf(xd) - MARGIN, 0.f);
            float thr = fminf(eA5, eB5);
            go = __any_sync(0xffffffffu, __fmul_rn(ax, ax) <= thr);
            j++;
        }
    }
#undef CAND_A
#undef CAND_B
#undef CAND_AX
#undef CAND_BX
#undef DIST
#undef INS6

    {   // exact two-pointer merge; tie -> lower sorted pos (deterministic)
#pragma unroll
        for (int s = 0; s < Kv; s++) {
            bool ta = (eA0 < eB0) || (eA0 == eB0 && jA0 < jB0);
            int sel = ta ? jA0 : jB0;
            snb[t * Kv + s] = s0s[sel];
            if (ta) { eA0=eA1; eA1=eA2; eA2=eA3; eA3=eA4; eA4=eA5; eA5=FLT_MAX;
                      jA0=jA1; jA1=jA2; jA2=jA3; jA3=jA4; jA4=jA5; }
            else    { eB0=eB1; eB1=eB2; eB2=eB3; eB3=eB4; eB4=eB5; eB5=FLT_MAX;
                      jB0=jB1; jB1=jB2; jB2=jB3; jB3=jB4; jB4=jB5; }
        }
    }
    __syncthreads();

    // ---- phase 3: thread t = dim d; two independent row-chains per iter ----
    const int d = t;
    const float4 wv = sW3[d];
    const ull w01 = f2pack(wv.x, wv.y);
    ull AB[Kv];
#pragma unroll
    for (int k = 0; k < Kv; k++) AB[k] = *(const ull*)&sAB[k * Dv + d];

    float acc = 0.f;
#pragma unroll 2
    for (int r = 0; r < RPB; r += 2) {
        float4 rdA = srow[r], rdB = srow[r + 1];
        const ulonglong2* nA = (const ulonglong2*)(snb + r * Kv);
        const ulonglong2* nB = (const ulonglong2*)(snb + (r + 1) * Kv);
        ulonglong2 a0 = nA[0], a1 = nA[1], a2 = nA[2];
        ulonglong2 b0 = nB[0], b1 = nB[1], b2 = nB[2];
        ull sA = f2pack(wv.w, __fmul_rn(rdA.z, wv.z));
        ull sB = f2pack(wv.w, __fmul_rn(rdB.z, wv.z));
        sA = f2fma(f2pack(rdA.x, rdA.y), w01, sA);
        sB = f2fma(f2pack(rdB.x, rdB.y), w01, sB);
        sA = f2fma(a0.x, AB[0], sA);  sB = f2fma(b0.x, AB[0], sB);
        sA = f2fma(a0.y, AB[1], sA);  sB = f2fma(b0.y, AB[1], sB);
        sA = f2fma(a1.x, AB[2], sA);  sB = f2fma(b1.x, AB[2], sB);
        sA = f2fma(a1.y, AB[3], sA);  sB = f2fma(b1.y, AB[3], sB);
        sA = f2fma(a2.x, AB[4], sA);  sB = f2fma(b2.x, AB[4], sB);
        sA = f2fma(a2.y, AB[5], sA);  sB = f2fma(b2.y, AB[5], sB);
        float loA, hiA, loB, hiB;
        f2unpack(sA, loA, hiA); f2unpack(sB, loB, hiB);
        float vA = __fadd_rn(loA, hiA);
        float vB = __fadd_rn(loB, hiB);
        vA = fmaxf(vA, 0.01f * vA);              // leaky_relu(0.01)
        vB = fmaxf(vB, 0.01f * vB);
        h_out[((size_t)b * 1025 + 1 + __float_as_int(rdA.w)) * Dv + d] = vA;
        h_out[((size_t)b * 1025 + 1 + __float_as_int(rdB.w)) * Dv + d] = vB;
        acc += vA; acc += vB;
    }
    g_partial[((size_t)b * CHUNKS + chunk) * Dv + d] = acc;

    // ---- fused tail: last finishing block computes depot row + means ----
    __threadfence();
    if (t == 0) sLast = (atomicAdd(&g_count, 1) == CHUNKS * Bv - 1) ? 1 : 0;
    __syncthreads();
    if (sLast) {
        float w0 = Wdep[t * 2 + 0], w1 = Wdep[t * 2 + 1], bd = bdep[t];
        for (int bb = 0; bb < Bv; bb++) {
            float v = bd;
            v = fmaf(depot[bb * 2 + 0], w0, v);
            v = fmaf(depot[bb * 2 + 1], w1, v);
            v = fmaxf(v, 0.01f * v);
            h_out[(size_t)bb * 1025 * Dv + t] = v;       // h[bb, 0, d]
            float s = v;
#pragma unroll
            for (int c = 0; c < CHUNKS; c++)
                s += g_partial[((size_t)bb * CHUNKS + c) * Dv + t];
            h_out[(size_t)Bv * 1025 * Dv + bb * Dv + t] = s / 1025.0f;
        }
        if (t == 0) g_count = 0;                 // reset for next graph replay
    }
}

// ---------------------------------------------------------------------------
extern "C" void kernel_launch(void* const* d_in, const int* in_sizes, int n_in,
                              void* d_out, int out_size)
{
    const float* loc      = (const float*)d_in[0];
    const float* deadline = (const float*)d_in[1];
    const float* depot    = (const float*)d_in[2];
    const float* W3d      = (const float*)d_in[3];
    const float* b3d      = (const float*)d_in[4];
    const float* W2d      = (const float*)d_in[5];
    const float* b2d      = (const float*)d_in[6];
    const float* Wnb      = (const float*)d_in[7];
    const float* bnb      = (const float*)d_in[8];
    const float* Wdep     = (const float*)d_in[9];
    const float* bdep     = (const float*)d_in[10];
    float* out = (float*)d_out;

    setup_kernel<<<Bv + 48, 512>>>(loc, deadline, W2d, b2d, Wnb);
    dim3 grid(CHUNKS, Bv);
    main_kernel<<<grid, THR>>>(W3d, b3d, bnb, depot, Wdep, bdep, out);
}

// round 14
// speedup vs baseline: 1.2306x; 1.0834x over previous
#include <cuda_runtime.h>
#include <float.h>

#define Bv 64
#define Nv 1024
#define Dv 128
#define Kv 6
#define CHUNKS 8          // 128 rows per main block, grid = 8 x 64 = 512
#define RPB 128
#define THR 128
#define MARGIN 0.001f     // > 1/1024 bucket width (counting-sort disorder bound)

typedef unsigned long long ull;

__device__ float  g_ABC[Kv * Dv * 3];           // [k][d][{A,B,C}]
__device__ float  g_partial[Bv * CHUNKS * Dv];  // [b][chunk][d]
__device__ float4 g_pts[Bv * Nv];               // (xb, yb, deadline, orig)
__device__ float2 g_p0[Bv * Nv];                // (x0, y0) sorted order
__device__ int    g_count;                      // completion counter

// ---- packed f32x2 helpers (per-half rn == scalar rounding) ----
__device__ __forceinline__ ull f2add(ull a, ull b) {
    ull r; asm("add.rn.f32x2 %0,%1,%2;" : "=l"(r) : "l"(a), "l"(b)); return r;
}
__device__ __forceinline__ ull f2mul(ull a, ull b) {
    ull r; asm("mul.rn.f32x2 %0,%1,%2;" : "=l"(r) : "l"(a), "l"(b)); return r;
}
__device__ __forceinline__ ull f2fma(ull a, ull b, ull c) {
    ull r; asm("fma.rn.f32x2 %0,%1,%2,%3;" : "=l"(r) : "l"(a), "l"(b), "l"(c)); return r;
}
__device__ __forceinline__ ull f2pack(float lo, float hi) {
    ull r; asm("mov.b64 %0,{%1,%2};" : "=l"(r) : "f"(lo), "f"(hi)); return r;
}
__device__ __forceinline__ void f2unpack(ull v, float& lo, float& hi) {
    asm("mov.b64 {%0,%1},%2;" : "=f"(lo), "=f"(hi) : "l"(v));
}

// ---------------------------------------------------------------------------
// Setup: blocks 0..63  -> per-batch counting sort by x-bucket (1024 buckets)
//        blocks 64..111 -> ABC weight fold (one warp per (k,d))
// ---------------------------------------------------------------------------
__global__ __launch_bounds__(512) void setup_kernel(
    const float* __restrict__ loc, const float* __restrict__ deadline,
    const float* __restrict__ W2d, const float* __restrict__ b2d,
    const float* __restrict__ Wnb)
{
    __shared__ int cnt[Nv];
    __shared__ int wsum[16];
    const int t = threadIdx.x;

    if (blockIdx.x >= Bv) {
        int wid  = (blockIdx.x - Bv) * 16 + (t >> 5);
        int k    = wid >> 7, d = wid & (Dv - 1);
        int lane = t & 31;
        const float4* w4 = (const float4*)(Wnb + (size_t)d * (Kv * Dv) + k * Dv);
        float4 v  = w4[lane];
        const float4* w2 = (const float4*)W2d;
        float4 p0 = w2[lane * 2], p1 = w2[lane * 2 + 1];
        float4 bb = ((const float4*)b2d)[lane];
        float A = fmaf(v.x, p0.x, fmaf(v.y, p0.z, fmaf(v.z, p1.x, v.w * p1.z)));
        float B = fmaf(v.x, p0.y, fmaf(v.y, p0.w, fmaf(v.z, p1.y, v.w * p1.w)));
        float C = fmaf(v.x, bb.x, fmaf(v.y, bb.y, fmaf(v.z, bb.z, v.w * bb.w)));
#pragma unroll
        for (int s = 16; s > 0; s >>= 1) {
            A += __shfl_xor_sync(0xffffffffu, A, s);
            B += __shfl_xor_sync(0xffffffffu, B, s);
            C += __shfl_xor_sync(0xffffffffu, C, s);
        }
        if (lane == 0) {
            int base = (k * Dv + d) * 3;
            g_ABC[base + 0] = A; g_ABC[base + 1] = B; g_ABC[base + 2] = C;
        }
        return;
    }

    const int b = blockIdx.x;
    const float2* lb = (const float2*)(loc + (size_t)b * Nv * 2);
    const float2* l0 = (const float2*)loc;

    cnt[t] = 0; cnt[t + 512] = 0;
    float2 pa = lb[t], pb = lb[t + 512];
    float2 qa = l0[t], qb = l0[t + 512];
    float dla = deadline[(size_t)b * Nv + t];
    float dlb = deadline[(size_t)b * Nv + t + 512];
    __syncthreads();
    int bka = min((int)(pa.x * 1024.0f), Nv - 1);
    int bkb = min((int)(pb.x * 1024.0f), Nv - 1);
    atomicAdd(&cnt[bka], 1);
    atomicAdd(&cnt[bkb], 1);
    __syncthreads();

    int c0 = cnt[2 * t], c1 = cnt[2 * t + 1];
    int s  = c0 + c1;
    int lane = t & 31;
    int v = s;
#pragma unroll
    for (int o = 1; o < 32; o <<= 1) {
        int u = __shfl_up_sync(0xffffffffu, v, o);
        if (lane >= o) v += u;
    }
    if (lane == 31) wsum[t >> 5] = v;
    __syncthreads();
    if (t < 16) {
        int wv = wsum[t], vv = wv;
#pragma unroll
        for (int o = 1; o < 16; o <<= 1) {
            int u = __shfl_up_sync(0x0000ffffu, vv, o);
            if (t >= o) vv += u;
        }
        wsum[t] = vv - wv;
    }
    __syncthreads();
    int excl = wsum[t >> 5] + (v - s);
    cnt[2 * t]     = excl;
    cnt[2 * t + 1] = excl + c0;
    __syncthreads();

    int posA = atomicAdd(&cnt[bka], 1);
    g_pts[(size_t)b * Nv + posA] = make_float4(pa.x, pa.y, dla, __int_as_float(t));
    g_p0[(size_t)b * Nv + posA]  = qa;
    int posB = atomicAdd(&cnt[bkb], 1);
    g_pts[(size_t)b * Nv + posB] = make_float4(pb.x, pb.y, dlb, __int_as_float(t + 512));
    g_p0[(size_t)b * Nv + posB]  = qb;
}

// ---------------------------------------------------------------------------
// Main: 128 threads = 4 warps; warp w owns rows [w*32, w*32+32); two-sided
// warp-uniform scan. Core: exact sorted insert. Wings: cheap filter against
// monotone upper bound ub (exact d5 of all flushed candidates) + per-lane
// smem ring buffer; flush through exact insert when any lane has >= 8
// pending. Result is the exact top-6 (same selection semantics as R8).
// ---------------------------------------------------------------------------
__global__ __launch_bounds__(THR) void main_kernel(
    const float* __restrict__ W3d, const float* __restrict__ b3d,
    const float* __restrict__ bnb,
    const float* __restrict__ depot, const float* __restrict__ Wdep,
    const float* __restrict__ bdep, float* __restrict__ h_out)
{
    __shared__ __align__(16) float2 sxyv[Nv];      // sorted batch-b coords  8 KB
    __shared__ __align__(16) float2 s0s[Nv];       // batch-0 coords, sorted 8 KB
    __shared__ float4 srow[RPB];                   // (x,y,deadline,orig)    2 KB
    __shared__ __align__(16) float2 snb[RPB * Kv]; // neighbor b0 coords     6 KB
    __shared__ float4 sW3[Dv];                     // (w0,w1,w2, base)       2 KB
    __shared__ __align__(16) float2 sAB[Kv * Dv];  // (A_k[d], B_k[d])       6 KB
    __shared__ float2 sbuf[16][THR];               // per-lane hit ring     16 KB
    __shared__ int    sLast;

    const int b = blockIdx.y, chunk = blockIdx.x, t = threadIdx.x;

    {
        const float4* gp = g_pts + (size_t)b * Nv;
        const float2* g0 = g_p0  + (size_t)b * Nv;
#pragma unroll
        for (int i = 0; i < Nv / THR; i++) {
            float4 q = gp[i * THR + t];
            sxyv[i * THR + t] = make_float2(q.x, q.y);
            s0s[i * THR + t]  = g0[i * THR + t];
        }
        srow[t] = gp[chunk * RPB + t];
    }
    {
        float sumC = 0.f;
#pragma unroll
        for (int k = 0; k < Kv; k++) {
            int base = (k * Dv + t) * 3;
            sAB[k * Dv + t] = make_float2(g_ABC[base], g_ABC[base + 1]);
            sumC += g_ABC[base + 2];
        }
        sW3[t] = make_float4(W3d[t * 3 + 0], W3d[t * 3 + 1], W3d[t * 3 + 2],
                             b3d[t] + bnb[t] + sumC);
    }
    __syncthreads();

    // ---- phase 2 ----
    const int w    = t >> 5;
    const int base = chunk * RPB + w * 32;
    const int p    = base + (t & 31);
    const float2 m = sxyv[p];
    const ull negm = f2pack(-m.x, -m.y);

    float e0 = FLT_MAX, e1 = FLT_MAX, e2 = FLT_MAX,
          e3 = FLT_MAX, e4 = FLT_MAX, e5 = FLT_MAX;
    int   j0 = 0, j1 = 0, j2 = 0, j3 = 0, j4 = 0, j5 = 0;

    // exact branchless sorted insert (strict <)
#define INS6(dd, cj)  do {                                                   \
        bool c0 = dd < e0, c1 = dd < e1, c2 = dd < e2,                       \
             c3 = dd < e3, c4 = dd < e4, c5 = dd < e5;                       \
        float m0 = fmaxf(e0, dd), m1 = fmaxf(e1, dd), m2 = fmaxf(e2, dd),    \
              m3 = fmaxf(e3, dd), m4 = fmaxf(e4, dd);                        \
        int   w0 = c0 ? j0 : cj, w1 = c1 ? j1 : cj, w2 = c2 ? j2 : cj,       \
              w3 = c3 ? j3 : cj, w4 = c4 ? j4 : cj;                          \
        e5 = c5 ? m4 : e5;  j5 = c5 ? w4 : j5;                               \
        e4 = c4 ? m3 : e4;  j4 = c4 ? w3 : j4;                               \
        e3 = c3 ? m2 : e3;  j3 = c3 ? w2 : j3;                               \
        e2 = c2 ? m1 : e2;  j2 = c2 ? w1 : j2;                               \
        e1 = c1 ? m0 : e1;  j1 = c1 ? w0 : j1;                               \
        e0 = c0 ? dd : e0;  j0 = c0 ? cj : j0;                               \
    } while (0)

#define DIST(jj, DD, DX) {                                                  \
        ull cvu  = *(const ull*)&sxyv[jj];                                  \
        ull diff = f2add(cvu, negm);                                        \
        ull sq   = f2mul(diff, diff);                                       \
        float qlo, qhi, dlo, dhi;                                           \
        f2unpack(sq, qlo, qhi);                                             \
        f2unpack(diff, dlo, dhi); (void)dhi;                                \
        DX = dlo;                                                           \
        DD = __fadd_rn(qlo, qhi);                                           \
    }

    {   // core 32 candidates, exact insert (self dd=0 self-inserts)
#pragma unroll 8
        for (int q = 0; q < 32; q++) {
            float dd, dx; DIST(base + q, dd, dx); (void)dx;
            INS6(dd, base + q);
        }
    }

    float ub  = e5;        // monotone upper bound on true d5
    int   cnt = 0;         // total buffered hits
    int   rb  = 0;         // flushed up to rb

    // cheap wing candidate: filter + unconditional ring store
#define WCAND(jj, DX) {                                                     \
        float dd; DIST(jj, dd, DX);                                         \
        sbuf[cnt & 15][t] = make_float2(dd, __int_as_float(jj));            \
        cnt += (dd < ub) ? 1 : 0;                                           \
    }

    // flush pending buffered hits through exact insert; tighten ub
#define FLUSH_CHECK()  do {                                                 \
        int pend = cnt - rb;                                                \
        if (__any_sync(0xffffffffu, pend >= 8)) {                           \
            int mxp = __reduce_max_sync(0xffffffffu, pend);                 \
            for (int kk = 0; kk < mxp; kk++) {                              \
                float2 e = sbuf[(rb + kk) & 15][t];                         \
                float dd = (kk < pend) ? e.x : FLT_MAX;                     \
                INS6(dd, __float_as_int(e.y));                              \
            }                                                               \
            rb = cnt; ub = e5;                                              \
        }                                                                   \
    } while (0)

    {   // leftward wing, groups of 8
        int j = base - 1; bool go = (j >= 0);
        while (go && j >= 7) {
            float xd;
            WCAND(j,   xd); WCAND(j-1, xd); WCAND(j-2, xd); WCAND(j-3, xd);
            WCAND(j-4, xd); WCAND(j-5, xd); WCAND(j-6, xd); WCAND(j-7, xd);
            float ax = fmaxf(fabsf(xd) - MARGIN, 0.f);
            go = __any_sync(0xffffffffu, __fmul_rn(ax, ax) <= ub);
            FLUSH_CHECK();
            j -= 8;
        }
        while (go && j >= 0) {
            float xd; WCAND(j, xd);
            float ax = fmaxf(fabsf(xd) - MARGIN, 0.f);
            go = __any_sync(0xffffffffu, __fmul_rn(ax, ax) <= ub);
            j--;
        }
        FLUSH_CHECK();   // bound pending before right wing
    }
    {   // rightward wing
        int j = base + 32; bool go = (j < Nv);
        while (go && j <= Nv - 8) {
            float xd;
            WCAND(j,   xd); WCAND(j+1, xd); WCAND(j+2, xd); WCAND(j+3, xd);
            WCAND(j+4, xd); WCAND(j+5, xd); WCAND(j+6, xd); WCAND(j+7, xd);
            float ax = fmaxf(fabsf(xd) - MARGIN, 0.f);
            go = __any_sync(0xffffffffu, __fmul_rn(ax, ax) <= ub);
            FLUSH_CHECK();
            j += 8;
        }
        while (go && j < Nv) {
            float xd; WCAND(j, xd);
            float ax = fmaxf(fabsf(xd) - MARGIN, 0.f);
            go = __any_sync(0xffffffffu, __fmul_rn(ax, ax) <= ub);
            j++;
        }
    }
    {   // final flush (unconditional)
        int pend = cnt - rb;
        int mxp = __reduce_max_sync(0xffffffffu, pend);
        for (int kk = 0; kk < mxp; kk++) {
            float2 e = sbuf[(rb + kk) & 15][t];
            float dd = (kk < pend) ? e.x : FLT_MAX;
            INS6(dd, __float_as_int(e.y));
        }
    }
#undef WCAND
#undef FLUSH_CHECK
#undef DIST
#undef INS6

    snb[t*Kv+0] = s0s[j0]; snb[t*Kv+1] = s0s[j1]; snb[t*Kv+2] = s0s[j2];
    snb[t*Kv+3] = s0s[j3]; snb[t*Kv+4] = s0s[j4]; snb[t*Kv+5] = s0s[j5];
    __syncthreads();

    // ---- phase 3: thread t = dim d; two independent row-chains per iter ----
    const int d = t;
    const float4 wv = sW3[d];
    const ull w01 = f2pack(wv.x, wv.y);
    ull AB[Kv];
#pragma unroll
    for (int k = 0; k < Kv; k++) AB[k] = *(const ull*)&sAB[k * Dv + d];

    float acc = 0.f;
#pragma unroll 2
    for (int r = 0; r < RPB; r += 2) {
        float4 rdA = srow[r], rdB = srow[r + 1];
        const ulonglong2* nA = (const ulonglong2*)(snb + r * Kv);
        const ulonglong2* nB = (const ulonglong2*)(snb + (r + 1) * Kv);
        ulonglong2 a0 = nA[0], a1 = nA[1], a2 = nA[2];
        ulonglong2 b0 = nB[0], b1 = nB[1], b2 = nB[2];
        ull sA = f2pack(wv.w, __fmul_rn(rdA.z, wv.z));
        ull sB = f2pack(wv.w, __fmul_rn(rdB.z, wv.z));
        sA = f2fma(f2pack(rdA.x, rdA.y), w01, sA);
        sB = f2fma(f2pack(rdB.x, rdB.y), w01, sB);
        sA = f2fma(a0.x, AB[0], sA);  sB = f2fma(b0.x, AB[0], sB);
        sA = f2fma(a0.y, AB[1], sA);  sB = f2fma(b0.y, AB[1], sB);
        sA = f2fma(a1.x, AB[2], sA);  sB = f2fma(b1.x, AB[2], sB);
        sA = f2fma(a1.y, AB[3], sA);  sB = f2fma(b1.y, AB[3], sB);
        sA = f2fma(a2.x, AB[4], sA);  sB = f2fma(b2.x, AB[4], sB);
        sA = f2fma(a2.y, AB[5], sA);  sB = f2fma(b2.y, AB[5], sB);
        float loA, hiA, loB, hiB;
        f2unpack(sA, loA, hiA); f2unpack(sB, loB, hiB);
        float vA = __fadd_rn(loA, hiA);
        float vB = __fadd_rn(loB, hiB);
        vA = fmaxf(vA, 0.01f * vA);              // leaky_relu(0.01)
        vB = fmaxf(vB, 0.01f * vB);
        h_out[((size_t)b * 1025 + 1 + __float_as_int(rdA.w)) * Dv + d] = vA;
        h_out[((size_t)b * 1025 + 1 + __float_as_int(rdB.w)) * Dv + d] = vB;
        acc += vA; acc += vB;
    }
    g_partial[((size_t)b * CHUNKS + chunk) * Dv + d] = acc;

    // ---- fused tail: last finishing block computes depot row + means ----
    __threadfence();
    if (t == 0) sLast = (atomicAdd(&g_count, 1) == CHUNKS * Bv - 1) ? 1 : 0;
    __syncthreads();
    if (sLast) {
        float w0 = Wdep[t * 2 + 0], w1 = Wdep[t * 2 + 1], bd = bdep[t];
        for (int bb = 0; bb < Bv; bb++) {
            float v = bd;
            v = fmaf(depot[bb * 2 + 0], w0, v);
            v = fmaf(depot[bb * 2 + 1], w1, v);
            v = fmaxf(v, 0.01f * v);
            h_out[(size_t)bb * 1025 * Dv + t] = v;       // h[bb, 0, d]
            float s = v;
#pragma unroll
            for (int c = 0; c < CHUNKS; c++)
                s += g_partial[((size_t)bb * CHUNKS + c) * Dv + t];
            h_out[(size_t)Bv * 1025 * Dv + bb * Dv + t] = s / 1025.0f;
        }
        if (t == 0) g_count = 0;                 // reset for next graph replay
    }
}

// ---------------------------------------------------------------------------
extern "C" void kernel_launch(void* const* d_in, const int* in_sizes, int n_in,
                              void* d_out, int out_size)
{
    const float* loc      = (const float*)d_in[0];
    const float* deadline = (const float*)d_in[1];
    const float* depot    = (const float*)d_in[2];
    const float* W3d      = (const float*)d_in[3];
    const float* b3d      = (const float*)d_in[4];
    const float* W2d      = (const float*)d_in[5];
    const float* b2d      = (const float*)d_in[6];
    const float* Wnb      = (const float*)d_in[7];
    const float* bnb      = (const float*)d_in[8];
    const float* Wdep     = (const float*)d_in[9];
    const float* bdep     = (const float*)d_in[10];
    float* out = (float*)d_out;

    setup_kernel<<<Bv + 48, 512>>>(loc, deadline, W2d, b2d, Wnb);
    dim3 grid(CHUNKS, Bv);
    main_kernel<<<grid, THR>>>(W3d, b3d, bnb, depot, Wdep, bdep, out);
}

// round 15
// speedup vs baseline: 1.3041x; 1.0597x over previous
#include <cuda_runtime.h>
#include <float.h>

#define Bv 64
#define Nv 1024
#define Dv 128
#define Kv 6
#define CHUNKS 8          // 128 rows per main block, grid = 8 x 64 = 512
#define RPB 128
#define THR 128
#define GW 12             // 12x12 cell grid
#define NC (GW * GW)      // 144 cells
#define CELLW (1.0f / 12.0f)

typedef unsigned long long ull;

__device__ float  g_ABC[Kv * Dv * 3];           // [k][d][{A,B,C}]
__device__ float  g_partial[Bv * CHUNKS * Dv];  // [b][chunk][d]
__device__ float4 g_pts[Bv * Nv];               // (x, y, deadline, orig) cell-sorted
__device__ float2 g_p0[Bv * Nv];                // (x0, y0) cell-sorted order
__device__ int    g_cs[Bv * (NC + 1)];          // cell start offsets
__device__ int    g_count;                      // completion counter

// ---- packed f32x2 helpers (per-half rn == scalar rounding) ----
__device__ __forceinline__ ull f2add(ull a, ull b) {
    ull r; asm("add.rn.f32x2 %0,%1,%2;" : "=l"(r) : "l"(a), "l"(b)); return r;
}
__device__ __forceinline__ ull f2mul(ull a, ull b) {
    ull r; asm("mul.rn.f32x2 %0,%1,%2;" : "=l"(r) : "l"(a), "l"(b)); return r;
}
__device__ __forceinline__ ull f2fma(ull a, ull b, ull c) {
    ull r; asm("fma.rn.f32x2 %0,%1,%2,%3;" : "=l"(r) : "l"(a), "l"(b), "l"(c)); return r;
}
__device__ __forceinline__ ull f2pack(float lo, float hi) {
    ull r; asm("mov.b64 %0,{%1,%2};" : "=l"(r) : "f"(lo), "f"(hi)); return r;
}
__device__ __forceinline__ void f2unpack(ull v, float& lo, float& hi) {
    asm("mov.b64 {%0,%1},%2;" : "=f"(lo), "=f"(hi) : "l"(v));
}

__device__ __forceinline__ int cell_of(float x, float y) {
    int cx = min((int)(x * 12.0f), GW - 1);
    int cy = min((int)(y * 12.0f), GW - 1);
    return cy * GW + cx;
}

// ---------------------------------------------------------------------------
// Setup: blocks 0..63  -> per-batch counting sort by 2-D cell (144 cells)
//        blocks 64..111 -> ABC weight fold (one warp per (k,d))
// ---------------------------------------------------------------------------
__global__ __launch_bounds__(512) void setup_kernel(
    const float* __restrict__ loc, const float* __restrict__ deadline,
    const float* __restrict__ W2d, const float* __restrict__ b2d,
    const float* __restrict__ Wnb)
{
    __shared__ int cnt[NC];
    __shared__ int cs[NC + 1];
    const int t = threadIdx.x;

    if (blockIdx.x >= Bv) {
        int wid  = (blockIdx.x - Bv) * 16 + (t >> 5);
        int k    = wid >> 7, d = wid & (Dv - 1);
        int lane = t & 31;
        const float4* w4 = (const float4*)(Wnb + (size_t)d * (Kv * Dv) + k * Dv);
        float4 v  = w4[lane];
        const float4* w2 = (const float4*)W2d;
        float4 p0 = w2[lane * 2], p1 = w2[lane * 2 + 1];
        float4 bb = ((const float4*)b2d)[lane];
        float A = fmaf(v.x, p0.x, fmaf(v.y, p0.z, fmaf(v.z, p1.x, v.w * p1.z)));
        float B = fmaf(v.x, p0.y, fmaf(v.y, p0.w, fmaf(v.z, p1.y, v.w * p1.w)));
        float C = fmaf(v.x, bb.x, fmaf(v.y, bb.y, fmaf(v.z, bb.z, v.w * bb.w)));
#pragma unroll
        for (int s = 16; s > 0; s >>= 1) {
            A += __shfl_xor_sync(0xffffffffu, A, s);
            B += __shfl_xor_sync(0xffffffffu, B, s);
            C += __shfl_xor_sync(0xffffffffu, C, s);
        }
        if (lane == 0) {
            int base = (k * Dv + d) * 3;
            g_ABC[base + 0] = A; g_ABC[base + 1] = B; g_ABC[base + 2] = C;
        }
        return;
    }

    const int b = blockIdx.x;
    const float2* lb = (const float2*)(loc + (size_t)b * Nv * 2);
    const float2* l0 = (const float2*)loc;

    if (t < NC) cnt[t] = 0;
    float2 pa = lb[t], pb = lb[t + 512];
    float2 qa = l0[t], qb = l0[t + 512];
    float dla = deadline[(size_t)b * Nv + t];
    float dlb = deadline[(size_t)b * Nv + t + 512];
    __syncthreads();
    int ca = cell_of(pa.x, pa.y);
    int cb = cell_of(pb.x, pb.y);
    atomicAdd(&cnt[ca], 1);
    atomicAdd(&cnt[cb], 1);
    __syncthreads();

    // warp-parallel exclusive scan over 144 counters (lane i owns 5 cells)
    if (t < 32) {
        int v0 = 0, v1 = 0, v2 = 0, v3 = 0, v4 = 0;
        int i0 = t * 5;
        if (i0 + 0 < NC) v0 = cnt[i0 + 0];
        if (i0 + 1 < NC) v1 = cnt[i0 + 1];
        if (i0 + 2 < NC) v2 = cnt[i0 + 2];
        if (i0 + 3 < NC) v3 = cnt[i0 + 3];
        if (i0 + 4 < NC) v4 = cnt[i0 + 4];
        int tot = v0 + v1 + v2 + v3 + v4;
        int run = tot;
#pragma unroll
        for (int o = 1; o < 32; o <<= 1) {
            int u = __shfl_up_sync(0xffffffffu, run, o);
            if (t >= o) run += u;
        }
        int off = run - tot;   // exclusive
        if (i0 + 0 <= NC) cs[i0 + 0] = off;
        if (i0 + 1 <= NC) cs[i0 + 1] = off + v0;
        if (i0 + 2 <= NC) cs[i0 + 2] = off + v0 + v1;
        if (i0 + 3 <= NC) cs[i0 + 3] = off + v0 + v1 + v2;
        if (i0 + 4 <= NC) cs[i0 + 4] = off + v0 + v1 + v2 + v3;
        if (t == 31) cs[NC] = off + tot;
    }
    __syncthreads();
    if (t < NC) cnt[t] = cs[t];            // scatter cursors
    if (t <= NC) g_cs[b * (NC + 1) + t] = cs[t];
    __syncthreads();

    int posA = atomicAdd(&cnt[ca], 1);
    g_pts[(size_t)b * Nv + posA] = make_float4(pa.x, pa.y, dla, __int_as_float(t));
    g_p0[(size_t)b * Nv + posA]  = qa;
    int posB = atomicAdd(&cnt[cb], 1);
    g_pts[(size_t)b * Nv + posB] = make_float4(pb.x, pb.y, dlb, __int_as_float(t + 512));
    g_p0[(size_t)b * Nv + posB]  = qb;
}

// ---------------------------------------------------------------------------
// Main: 128 threads = 128 cell-sorted rows. Each thread scans its 3x3 cell
// neighborhood (3 contiguous spans), exact strict-< top-6 insert; geometric
// margin test drives exact ring expansion (rare). Phase 3 + fused tail as R14.
// ---------------------------------------------------------------------------
__global__ __launch_bounds__(THR) void main_kernel(
    const float* __restrict__ W3d, const float* __restrict__ b3d,
    const float* __restrict__ bnb,
    const float* __restrict__ depot, const float* __restrict__ Wdep,
    const float* __restrict__ bdep, float* __restrict__ h_out)
{
    __shared__ __align__(16) float2 sxyv[Nv];      // cell-sorted coords     8 KB
    __shared__ __align__(16) float2 s0s[Nv];       // batch-0 coords         8 KB
    __shared__ int    scs[NC + 1];                 // cell starts          0.6 KB
    __shared__ float4 srow[RPB];                   // (x,y,deadline,orig)    2 KB
    __shared__ __align__(16) float2 snb[RPB * Kv]; // neighbor b0 coords     6 KB
    __shared__ float4 sW3[Dv];                     // (w0,w1,w2, base)       2 KB
    __shared__ __align__(16) float2 sAB[Kv * Dv];  // (A_k[d], B_k[d])       6 KB
    __shared__ int    sLast;

    const int b = blockIdx.y, chunk = blockIdx.x, t = threadIdx.x;

    {
        const float4* gp = g_pts + (size_t)b * Nv;
        const float2* g0 = g_p0  + (size_t)b * Nv;
#pragma unroll
        for (int i = 0; i < Nv / THR; i++) {
            float4 q = gp[i * THR + t];
            sxyv[i * THR + t] = make_float2(q.x, q.y);
            s0s[i * THR + t]  = g0[i * THR + t];
        }
        srow[t] = gp[chunk * RPB + t];
        for (int i = t; i <= NC; i += THR) scs[i] = g_cs[b * (NC + 1) + i];
    }
    {
        float sumC = 0.f;
#pragma unroll
        for (int k = 0; k < Kv; k++) {
            int base = (k * Dv + t) * 3;
            sAB[k * Dv + t] = make_float2(g_ABC[base], g_ABC[base + 1]);
            sumC += g_ABC[base + 2];
        }
        sW3[t] = make_float4(W3d[t * 3 + 0], W3d[t * 3 + 1], W3d[t * 3 + 2],
                             b3d[t] + bnb[t] + sumC);
    }
    __syncthreads();

    // ---- phase 2: 3x3 cell scan with exact ring expansion ----
    const float4 me = srow[t];
    const float mx = me.x, my = me.y;
    const int cx = min((int)(mx * 12.0f), GW - 1);
    const int cy = min((int)(my * 12.0f), GW - 1);
    const ull negm = f2pack(-mx, -my);

    float e0 = FLT_MAX, e1 = FLT_MAX, e2 = FLT_MAX,
          e3 = FLT_MAX, e4 = FLT_MAX, e5 = FLT_MAX;
    int   j0 = 0, j1 = 0, j2 = 0, j3 = 0, j4 = 0, j5 = 0;

#define INS6(dd, cj)  do {                                                   \
        bool c0 = dd < e0, c1 = dd < e1, c2 = dd < e2,                       \
             c3 = dd < e3, c4 = dd < e4, c5 = dd < e5;                       \
        float m0 = fmaxf(e0, dd), m1 = fmaxf(e1, dd), m2 = fmaxf(e2, dd),    \
              m3 = fmaxf(e3, dd), m4 = fmaxf(e4, dd);                        \
        int   w0 = c0 ? j0 : cj, w1 = c1 ? j1 : cj, w2 = c2 ? j2 : cj,       \
              w3 = c3 ? j3 : cj, w4 = c4 ? j4 : cj;                          \
        e5 = c5 ? m4 : e5;  j5 = c5 ? w4 : j5;                               \
        e4 = c4 ? m3 : e4;  j4 = c4 ? w3 : j4;                               \
        e3 = c3 ? m2 : e3;  j3 = c3 ? w2 : j3;                               \
        e2 = c2 ? m1 : e2;  j2 = c2 ? w1 : j2;                               \
        e1 = c1 ? m0 : e1;  j1 = c1 ? w0 : j1;                               \
        e0 = c0 ? dd : e0;  j0 = c0 ? cj : j0;                               \
    } while (0)

#define SPAN(JS, JE)  for (int j = (JS); j < (JE); j++) {                    \
        ull cvu  = *(const ull*)&sxyv[j];                                    \
        ull diff = f2add(cvu, negm);                                         \
        ull sq   = f2mul(diff, diff);                                        \
        float qlo, qhi; f2unpack(sq, qlo, qhi);                              \
        float dd = __fadd_rn(qlo, qhi);                                      \
        INS6(dd, j);                                                         \
    }

    {   // 3x3 neighborhood: three contiguous spans
        int xlo = max(cx - 1, 0), xhi = min(cx + 1, GW - 1);
#pragma unroll
        for (int dy = -1; dy <= 1; dy++) {
            int yy = cy + dy;
            if ((unsigned)yy < GW) {
                int js = scs[yy * GW + xlo];
                int je = scs[yy * GW + xhi + 1];
                SPAN(js, je);
            }
        }
    }

    {   // exact ring expansion (rare): widen until margin^2 >= e5
        int R = 1;
        float ml = (cx - R >= 0)      ? mx - (float)(cx - R) * CELLW : 1e30f;
        float mr = (cx + R <= GW - 1) ? (float)(cx + R + 1) * CELLW - mx : 1e30f;
        float mb = (cy - R >= 0)      ? my - (float)(cy - R) * CELLW : 1e30f;
        float mt = (cy + R <= GW - 1) ? (float)(cy + R + 1) * CELLW - my : 1e30f;
        float mg = fmaxf(fminf(fminf(ml, mr), fminf(mb, mt)) - 1e-6f, 0.f);
        bool need = e5 > mg * mg;
        while (__any_sync(0xffffffffu, need) && R < GW) {
            R++;
            if (need) {
                int xlo = max(cx - R, 0), xhi = min(cx + R, GW - 1);
                int ytop = cy - R, ybot = cy + R;
                if (ytop >= 0)     { SPAN(scs[ytop * GW + xlo], scs[ytop * GW + xhi + 1]); }
                if (ybot <= GW - 1){ SPAN(scs[ybot * GW + xlo], scs[ybot * GW + xhi + 1]); }
                int yy0 = max(cy - R + 1, 0), yy1 = min(cy + R - 1, GW - 1);
                for (int yy = yy0; yy <= yy1; yy++) {
                    if (cx - R >= 0)     { SPAN(scs[yy * GW + cx - R], scs[yy * GW + cx - R + 1]); }
                    if (cx + R <= GW - 1){ SPAN(scs[yy * GW + cx + R], scs[yy * GW + cx + R + 1]); }
                }
                ml = (cx - R >= 0)      ? mx - (float)(cx - R) * CELLW : 1e30f;
                mr = (cx + R <= GW - 1) ? (float)(cx + R + 1) * CELLW - mx : 1e30f;
                mb = (cy - R >= 0)      ? my - (float)(cy - R) * CELLW : 1e30f;
                mt = (cy + R <= GW - 1) ? (float)(cy + R + 1) * CELLW - my : 1e30f;
                mg = fmaxf(fminf(fminf(ml, mr), fminf(mb, mt)) - 1e-6f, 0.f);
                need = e5 > mg * mg;
            }
        }
    }
#undef SPAN
#undef INS6

    snb[t*Kv+0] = s0s[j0]; snb[t*Kv+1] = s0s[j1]; snb[t*Kv+2] = s0s[j2];
    snb[t*Kv+3] = s0s[j3]; snb[t*Kv+4] = s0s[j4]; snb[t*Kv+5] = s0s[j5];
    __syncthreads();

    // ---- phase 3: thread t = dim d; two independent row-chains per iter ----
    const int d = t;
    const float4 wv = sW3[d];
    const ull w01 = f2pack(wv.x, wv.y);
    ull AB[Kv];
#pragma unroll
    for (int k = 0; k < Kv; k++) AB[k] = *(const ull*)&sAB[k * Dv + d];

    float acc = 0.f;
#pragma unroll 2
    for (int r = 0; r < RPB; r += 2) {
        float4 rdA = srow[r], rdB = srow[r + 1];
        const ulonglong2* nA = (const ulonglong2*)(snb + r * Kv);
        const ulonglong2* nB = (const ulonglong2*)(snb + (r + 1) * Kv);
        ulonglong2 a0 = nA[0], a1 = nA[1], a2 = nA[2];
        ulonglong2 b0 = nB[0], b1 = nB[1], b2 = nB[2];
        ull sA = f2pack(wv.w, __fmul_rn(rdA.z, wv.z));
        ull sB = f2pack(wv.w, __fmul_rn(rdB.z, wv.z));
        sA = f2fma(f2pack(rdA.x, rdA.y), w01, sA);
        sB = f2fma(f2pack(rdB.x, rdB.y), w01, sB);
        sA = f2fma(a0.x, AB[0], sA);  sB = f2fma(b0.x, AB[0], sB);
        sA = f2fma(a0.y, AB[1], sA);  sB = f2fma(b0.y, AB[1], sB);
        sA = f2fma(a1.x, AB[2], sA);  sB = f2fma(b1.x, AB[2], sB);
        sA = f2fma(a1.y, AB[3], sA);  sB = f2fma(b1.y, AB[3], sB);
        sA = f2fma(a2.x, AB[4], sA);  sB = f2fma(b2.x, AB[4], sB);
        sA = f2fma(a2.y, AB[5], sA);  sB = f2fma(b2.y, AB[5], sB);
        float loA, hiA, loB, hiB;
        f2unpack(sA, loA, hiA); f2unpack(sB, loB, hiB);
        float vA = __fadd_rn(loA, hiA);
        float vB = __fadd_rn(loB, hiB);
        vA = fmaxf(vA, 0.01f * vA);              // leaky_relu(0.01)
        vB = fmaxf(vB, 0.01f * vB);
        h_out[((size_t)b * 1025 + 1 + __float_as_int(rdA.w)) * Dv + d] = vA;
        h_out[((size_t)b * 1025 + 1 + __float_as_int(rdB.w)) * Dv + d] = vB;
        acc += vA; acc += vB;
    }
    g_partial[((size_t)b * CHUNKS + chunk) * Dv + d] = acc;

    // ---- fused tail: last finishing block computes depot row + means ----
    __threadfence();
    if (t == 0) sLast = (atomicAdd(&g_count, 1) == CHUNKS * Bv - 1) ? 1 : 0;
    __syncthreads();
    if (sLast) {
        float w0 = Wdep[t * 2 + 0], w1 = Wdep[t * 2 + 1], bd = bdep[t];
        for (int bb = 0; bb < Bv; bb++) {
            float v = bd;
            v = fmaf(depot[bb * 2 + 0], w0, v);
            v = fmaf(depot[bb * 2 + 1], w1, v);
            v = fmaxf(v, 0.01f * v);
            h_out[(size_t)bb * 1025 * Dv + t] = v;       // h[bb, 0, d]
            float s = v;
#pragma unroll
            for (int c = 0; c < CHUNKS; c++)
                s += g_partial[((size_t)bb * CHUNKS + c) * Dv + t];
            h_out[(size_t)Bv * 1025 * Dv + bb * Dv + t] = s / 1025.0f;
        }
        if (t == 0) g_count = 0;                 // reset for next graph replay
    }
}

// ---------------------------------------------------------------------------
extern "C" void kernel_launch(void* const* d_in, const int* in_sizes, int n_in,
                              void* d_out, int out_size)
{
    const float* loc      = (const float*)d_in[0];
    const float* deadline = (const float*)d_in[1];
    const float* depot    = (const float*)d_in[2];
    const float* W3d      = (const float*)d_in[3];
    const float* b3d      = (const float*)d_in[4];
    const float* W2d      = (const float*)d_in[5];
    const float* b2d      = (const float*)d_in[6];
    const float* Wnb      = (const float*)d_in[7];
    const float* bnb      = (const float*)d_in[8];
    const float* Wdep     = (const float*)d_in[9];
    const float* bdep     = (const float*)d_in[10];
    float* out = (float*)d_out;

    setup_kernel<<<Bv + 48, 512>>>(loc, deadline, W2d, b2d, Wnb);
    dim3 grid(CHUNKS, Bv);
    main_kernel<<<grid, THR>>>(W3d, b3d, bnb, depot, Wdep, bdep, out);
}